// round 9
// baseline (speedup 1.0000x reference)
#include <cuda_runtime.h>
#include <cuda_bf16.h>
#include <math.h>
#include <stdint.h>

// Problem constants
#define KDIM 128
#define BDIM 16
#define LDIM 8192
#define NF   256            // fine grid (oversampling sigma = 2)
#define WHALF 2.5f          // window half-width (w = 5)
#define BETA  11.5f         // ES beta = 2.30 * w
#define PI_F 3.14159265358979f

#define FSTRIDE 272         // fine-grid row stride (256 + 8 halo + 8 pad)
#define FBATCH  (NF * FSTRIDE)
#define LUTN 1600           // window LUT entries, step 1/512

// Scratch (device globals; no cudaMalloc allowed)
__device__ float    d_phi[65];
__device__ float    d_ctab[256];
__device__ float    d_cos256[256];
__device__ float    d_corner[BDIM];
__device__ float2   d_wlut[LUTN];
__device__ float    d_g[BDIM * KDIM * NF];
__device__ float    d_f[BDIM * FBATCH];
// mma fragment storage (bf16x2 packed): A2 = c-circulant [16 mt][8 kt][32 lane][4 regs]
__device__ uint32_t d_A2h[16384];
__device__ uint32_t d_A2l[16384];
// B = g frags [16 b][32 vt][8 kt][32 lane][2 regs]
__device__ uint32_t d_Bh[262144];
__device__ uint32_t d_Bl[262144];

__device__ __forceinline__ float es_win(float dist) {
    float z = dist * (1.0f / WHALF);
    float t = 1.0f - z * z;
    if (t <= 0.0f) return 0.0f;
    return expf(BETA * (sqrtf(t) - 1.0f));
}

__device__ __forceinline__ uint32_t packbf(float x, float y) {
    __nv_bfloat162 t = __floats2bfloat162_rn(x, y);
    return *(uint32_t*)&t;
}
__device__ __forceinline__ float bfhi(float x) {
    return __bfloat162float(__float2bfloat16_rn(x));
}

__device__ __forceinline__ void mma_bf16(float4& d, uint4 a, uint2 b) {
    asm("mma.sync.aligned.m16n8k16.row.col.f32.bf16.bf16.f32 "
        "{%0,%1,%2,%3},{%4,%5,%6,%7},{%8,%9},{%0,%1,%2,%3};"
        : "+f"(d.x), "+f"(d.y), "+f"(d.z), "+f"(d.w)
        : "r"(a.x), "r"(a.y), "r"(a.z), "r"(a.w), "r"(b.x), "r"(b.y));
}

// ---------------------------------------------------------------------------
// Prep kernel, grid 89 x 256:
//  blocks 0..64  : Phi_k quadrature    blocks 65..71 : window LUT
//  blocks 72..87 : per-batch corner    block 88      : cos table
// ---------------------------------------------------------------------------
__global__ void prep_kernel(const float* __restrict__ psi) {
    int bid = blockIdx.x;
    int tid = threadIdx.x;

    if (bid < 65) {
        __shared__ float red[256];
        const int NQ = 512;
        float h = (2.0f * WHALF) / NQ;
        float k = (float)bid;
        float acc = 0.0f;
        #pragma unroll
        for (int r = 0; r < 2; r++) {
            int i = tid + r * 256;
            float t = -WHALF + (i + 0.5f) * h;
            acc += es_win(fabsf(t)) * cospif(k * t * (1.0f / 128.0f));
        }
        red[tid] = acc;
        __syncthreads();
        for (int s = 128; s > 0; s >>= 1) {
            if (tid < s) red[tid] += red[tid + s];
            __syncthreads();
        }
        if (tid == 0) d_phi[bid] = red[0] * h;
    } else if (bid < 72) {
        int i = (bid - 65) * 256 + tid;
        if (i < LUTN) {
            float h = 1.0f / 512.0f;
            float v0 = es_win((float)i * h);
            float v1 = es_win((float)(i + 1) * h);
            d_wlut[i] = make_float2(v0, v1 - v0);
        }
    } else if (bid < 88) {
        __shared__ float red[256];
        int b = bid - 72;
        const float* p = psi + b * (KDIM * KDIM);
        float acc = 0.0f;
        for (int idx = tid; idx < KDIM * KDIM; idx += 256) {
            float v = p[idx];
            int par = ((idx >> 7) ^ idx) & 1;
            acc += par ? -v : v;
        }
        red[tid] = acc;
        __syncthreads();
        for (int s = 128; s > 0; s >>= 1) {
            if (tid < s) red[tid] += red[tid + s];
            __syncthreads();
        }
        if (tid == 0) d_corner[b] = red[0];
    } else {
        d_cos256[tid] = cospif((float)tid * (1.0f / 128.0f));
    }
}

// ---------------------------------------------------------------------------
// c-table combine: trig via cos table.
// ---------------------------------------------------------------------------
__global__ void ctab_kernel() {
    __shared__ float sD[65];
    __shared__ float sc[256];
    int tid = threadIdx.x;
    sc[tid] = d_cos256[tid];
    if (tid < 65) sD[tid] = 1.0f / d_phi[tid];
    __syncthreads();
    int d = tid;
    float s = sD[0];
    #pragma unroll 8
    for (int k = 1; k < 64; k++) {
        s = fmaf(2.0f * sD[k], sc[(k * d) & 255], s);
    }
    s = fmaf(sD[64], sc[(64 * d) & 255], s);
    d_ctab[d] = s * (1.0f / 128.0f);
}

// ---------------------------------------------------------------------------
// A2 fragment generation: A2[u][m] = c[(u - 2m) & 255], split hi/lo bf16,
// packed in m16n8k16 A-fragment layout: [mt][kt][lane][4 regs].
// reg r: row = mt*16 + (lane>>2) + (r&1)*8, cols = kt*16 + 2*(lane&3) + (r>>1)*8 + {0,1}
// grid: 16 x 256 (4096 threads)
// ---------------------------------------------------------------------------
__global__ void a2gen_kernel() {
    int t = blockIdx.x * 256 + threadIdx.x;
    if (t >= 4096) return;
    int lane = t & 31, kt = (t >> 5) & 7, mt = t >> 8;
    int g = lane >> 2, tg = lane & 3;
    #pragma unroll
    for (int r = 0; r < 4; r++) {
        int u  = mt * 16 + g + (r & 1) * 8;
        int c0 = kt * 16 + 2 * tg + ((r >> 1) & 1) * 8;
        float x0 = d_ctab[(u - 2 * c0) & 255];
        float x1 = d_ctab[(u - 2 * (c0 + 1)) & 255];
        float h0 = bfhi(x0), h1 = bfhi(x1);
        d_A2h[t * 4 + r] = packbf(h0, h1);
        d_A2l[t * 4 + r] = packbf(x0 - h0, x1 - h1);
    }
}

// ---------------------------------------------------------------------------
// Stage 1: g[b,m,v] = sum_n psi[b,m,n] * c[(v - 2n) mod 256]  (scalar, proven)
// tile 32(m) x 64(v), 128 threads, micro 4x4. grid (4 v, 4 m, 16 b)
// ---------------------------------------------------------------------------
__global__ void __launch_bounds__(128) stage1_kernel(const float* __restrict__ psi) {
    __shared__ float cs2[512];
    __shared__ __align__(16) float As[32][36];   // [n-local][m-local] transposed
    int b  = blockIdx.z;
    int m0 = blockIdx.y * 32;
    int v0 = blockIdx.x * 64;
    int tid = threadIdx.x;
    #pragma unroll
    for (int i = 0; i < 4; i++)
        cs2[tid + i * 128] = d_ctab[(tid + i * 128) & 255];
    int tx = tid & 15, ty = tid >> 4;
    float acc[4][4] = {};
    const float* P = psi + b * (KDIM * KDIM);

    for (int n0 = 0; n0 < KDIM; n0 += 32) {
        __syncthreads();
        #pragma unroll
        for (int i = 0; i < 2; i++) {
            int u = tid + i * 128;
            int ml = u >> 3, n4 = (u & 7) * 4;
            float4 a = *(const float4*)&P[(m0 + ml) * KDIM + n0 + n4];
            As[n4 + 0][ml] = a.x;
            As[n4 + 1][ml] = a.y;
            As[n4 + 2][ml] = a.z;
            As[n4 + 3][ml] = a.w;
        }
        __syncthreads();
        int bbase = v0 + tx * 4 + 256 - 2 * n0;
        #pragma unroll
        for (int nk = 0; nk < 32; nk++) {
            float4 a  = *(const float4*)&As[nk][ty * 4];
            int bi = bbase - 2 * nk;
            float2 p0 = *(const float2*)&cs2[bi];
            float2 p1 = *(const float2*)&cs2[bi + 2];
            float av[4] = {a.x, a.y, a.z, a.w};
            float bv[4] = {p0.x, p0.y, p1.x, p1.y};
            #pragma unroll
            for (int i = 0; i < 4; i++)
                #pragma unroll
                for (int j = 0; j < 4; j++)
                    acc[i][j] = fmaf(av[i], bv[j], acc[i][j]);
        }
    }
    float* G = d_g + b * (KDIM * NF);
    #pragma unroll
    for (int i = 0; i < 4; i++) {
        float4 o = make_float4(acc[i][0], acc[i][1], acc[i][2], acc[i][3]);
        *(float4*)&G[(m0 + ty * 4 + i) * NF + v0 + tx * 4] = o;
    }
}

// ---------------------------------------------------------------------------
// Repack: g -> bf16 hi/lo B-fragments [b][vt][kt][lane][2].
// b0 = {g[m0][v], g[m0+1][v]}, b1 = {g[m0+8][v], g[m0+9][v]}
//   with v = vt*8 + (lane>>2), m0 = kt*16 + 2*(lane&3).
// grid: 512 x 256 (131072 threads)
// ---------------------------------------------------------------------------
__global__ void repack_kernel() {
    int t = blockIdx.x * 256 + threadIdx.x;
    int lane = t & 31;
    int kt   = (t >> 5) & 7;
    int vt   = (t >> 8) & 31;
    int b    = t >> 13;
    int g = lane >> 2, tg = lane & 3;
    int v  = vt * 8 + g;
    int m0 = kt * 16 + 2 * tg;
    const float* G = d_g + b * (KDIM * NF);
    float g00 = G[m0 * NF + v];
    float g01 = G[(m0 + 1) * NF + v];
    float g10 = G[(m0 + 8) * NF + v];
    float g11 = G[(m0 + 9) * NF + v];
    float h00 = bfhi(g00), h01 = bfhi(g01), h10 = bfhi(g10), h11 = bfhi(g11);
    d_Bh[2 * t + 0] = packbf(h00, h01);
    d_Bh[2 * t + 1] = packbf(h10, h11);
    d_Bl[2 * t + 0] = packbf(g00 - h00, g01 - h01);
    d_Bl[2 * t + 1] = packbf(g10 - h10, g11 - h11);
}

// ---------------------------------------------------------------------------
// Stage 2 (tensor): f[b,u,v] = sum_m A2[u,m] g[m,v] via bf16 2-split mma.
// Block: 128 threads = 4 warps (2x2); warp: 2 u-tiles x 4 v-tiles (32u x 32v).
// grid: (4 v, 4 u, 16 b). Writes padded layout (+4 x offset) and x halo.
// ---------------------------------------------------------------------------
__global__ void __launch_bounds__(128) stage2_mma_kernel() {
    int b   = blockIdx.z;
    int u0t = blockIdx.y * 4;     // 4 u-tiles (of 16) per block
    int v0t = blockIdx.x * 8;     // 8 v-tiles (of 8) per block
    int warp = threadIdx.x >> 5, lane = threadIdx.x & 31;
    int wu = warp >> 1, wv = warp & 1;
    int mtb = u0t + wu * 2;
    int vtb = v0t + wv * 4;
    int g = lane >> 2, tg = lane & 3;

    float4 d[2][4];
    #pragma unroll
    for (int i = 0; i < 2; i++)
        #pragma unroll
        for (int j = 0; j < 4; j++)
            d[i][j] = make_float4(0.f, 0.f, 0.f, 0.f);

    const uint4* A2h = (const uint4*)d_A2h;
    const uint4* A2l = (const uint4*)d_A2l;
    const uint2* Bh  = (const uint2*)d_Bh;
    const uint2* Bl  = (const uint2*)d_Bl;

    #pragma unroll 2
    for (int kt = 0; kt < 8; kt++) {
        uint4 ah[2], al[2];
        #pragma unroll
        for (int i = 0; i < 2; i++) {
            int idx = ((mtb + i) * 8 + kt) * 32 + lane;
            ah[i] = A2h[idx];
            al[i] = A2l[idx];
        }
        uint2 bh[4], bl[4];
        #pragma unroll
        for (int j = 0; j < 4; j++) {
            int idx = ((b * 32 + vtb + j) * 8 + kt) * 32 + lane;
            bh[j] = Bh[idx];
            bl[j] = Bl[idx];
        }
        #pragma unroll
        for (int i = 0; i < 2; i++)
            #pragma unroll
            for (int j = 0; j < 4; j++) {
                mma_bf16(d[i][j], ah[i], bh[j]);
                mma_bf16(d[i][j], ah[i], bl[j]);
                mma_bf16(d[i][j], al[i], bh[j]);
            }
    }

    // epilogue: C frag -> padded fine grid (+ halos)
    float* F = d_f + b * FBATCH;
    #pragma unroll
    for (int i = 0; i < 2; i++) {
        int r0 = (mtb + i) * 16 + g;
        int r1 = r0 + 8;
        #pragma unroll
        for (int j = 0; j < 4; j++) {
            int v = (vtb + j) * 8 + 2 * tg;       // even, in [0,256)
            float2 lo = make_float2(d[i][j].x, d[i][j].y);
            float2 hi = make_float2(d[i][j].z, d[i][j].w);
            *(float2*)&F[r0 * FSTRIDE + v + 4] = lo;
            *(float2*)&F[r1 * FSTRIDE + v + 4] = hi;
            if (v < 4) {
                *(float2*)&F[r0 * FSTRIDE + 260 + v] = lo;
                *(float2*)&F[r1 * FSTRIDE + 260 + v] = hi;
            }
            if (v >= 252) {
                *(float2*)&F[r0 * FSTRIDE + v - 252] = lo;
                *(float2*)&F[r1 * FSTRIDE + v - 252] = hi;
            }
        }
    }
}

// ---------------------------------------------------------------------------
// Interpolation: one thread per point, w=5 ES window via shared LUT.
// ---------------------------------------------------------------------------
__global__ void interp_kernel(const float* __restrict__ x0,
                              const float* __restrict__ y0,
                              float* __restrict__ out) {
    __shared__ float2 slut[LUTN];
    int tid = threadIdx.x;
    for (int i = tid; i < LUTN; i += 256) slut[i] = d_wlut[i];
    __syncthreads();

    int p = blockIdx.x * 256 + tid;
    int b = p >> 13;
    float x = x0[p], y = y0[p];
    float txr = x * (128.0f / PI_F);
    float tyr = y * (128.0f / PI_F);
    float tx = txr + 256.0f;
    float ty = tyr + 256.0f;
    if (tx >= 256.0f) tx -= 256.0f;
    if (ty >= 256.0f) ty -= 256.0f;

    float fx = floorf(tx), fy = floorf(ty);
    int ix0 = (int)fx, iy0 = (int)fy;
    float dx = tx - fx, dy = ty - fy;

    int ic0 = ix0 - 2 + (dx >= 0.5f);
    int xb  = ic0 & ~3;
    int ir0 = iy0 - 2 + (dy >= 0.5f);

    float wx[8];
    #pragma unroll
    for (int j = 0; j < 8; j++) {
        float d  = fabsf(tx - (float)(xb + j));
        float fi = d * 512.0f;
        int idx  = (int)fi;
        float fr = fi - (float)idx;
        if (idx > LUTN - 1) { idx = LUTN - 1; fr = 0.0f; }
        float2 e = slut[idx];
        wx[j] = fmaf(fr, e.y, e.x);
    }
    float wy[5];
    #pragma unroll
    for (int a = 0; a < 5; a++) {
        float d  = fabsf(ty - (float)(ir0 + a));
        float fi = d * 512.0f;
        int idx  = (int)fi;
        float fr = fi - (float)idx;
        if (idx > LUTN - 1) { idx = LUTN - 1; fr = 0.0f; }
        float2 e = slut[idx];
        wy[a] = fmaf(fr, e.y, e.x);
    }

    const float* Fb = d_f + b * FBATCH;
    float acc = 0.0f;
    #pragma unroll
    for (int a = 0; a < 5; a++) {
        int row = (ir0 + a) & 255;
        const float4* rp = (const float4*)(Fb + row * FSTRIDE + xb + 4);
        float4 A = __ldg(rp);
        float4 Bv = __ldg(rp + 1);
        float rs = wx[0] * A.x + wx[1] * A.y + wx[2] * A.z + wx[3] * A.w
                 + wx[4] * Bv.x + wx[5] * Bv.y + wx[6] * Bv.z + wx[7] * Bv.w;
        acc = fmaf(wy[a], rs, acc);
    }

    float corr = d_corner[b] * (1.0f / 16384.0f) *
                 sinpif(0.5f * txr) * sinpif(0.5f * tyr);
    out[p] = acc - corr;
}

// ---------------------------------------------------------------------------
extern "C" void kernel_launch(void* const* d_in, const int* in_sizes, int n_in,
                              void* d_out, int out_size) {
    const float* x0  = (const float*)d_in[0];
    const float* y0  = (const float*)d_in[1];
    const float* psi = (const float*)d_in[2];
    float* out = (float*)d_out;

    prep_kernel<<<89, 256>>>(psi);
    ctab_kernel<<<1, 256>>>();
    a2gen_kernel<<<16, 256>>>();
    stage1_kernel<<<dim3(4, 4, BDIM), 128>>>(psi);
    repack_kernel<<<512, 256>>>();
    stage2_mma_kernel<<<dim3(4, 4, BDIM), 128>>>();
    interp_kernel<<<512, 256>>>(x0, y0, out);
}